// round 13
// baseline (speedup 1.0000x reference)
#include <cuda_runtime.h>
#include <cuda_fp16.h>
#include <math.h>

// Radon forward projection, 512x512 img -> [512,512] sinogram (both axes flipped).
// R11: per-angle precompute table (kills per-warp sincos + clip divisions),
//      packed HFMA2 y-blend (one op interpolates both columns), reg-capped.
//      Memory layout unchanged: fp16x2 quad tables, 5 shears x 2 orients
//      (35 MB, L2-resident), one LDG.64 per bilinear sample.

#define IMG_N   512
#define N_ANG   512
#define N_DET   512
#define N_SAMP  256

#define PAD     3
#define TW      (IMG_N + 2*PAD + 2)     // 520

#define TOT_ROWS 8320                   // 2 orients x (1040+780+520+780+1040)

// entry: .x = half2(q00,q01) (top row), .y = half2(q10,q11) (bottom row)
__device__ uint2 g_tabs[TOT_ROWS * TW];     // 34.6 MB

// row starts for (orient, kn): orient*5 + (kn+2)
__device__ __constant__ int c_rowstart[10] =
    {0, 1040, 1820, 2340, 3120,  4160, 5200, 5980, 6500, 7280};
__device__ __constant__ int c_off[5] = {519, 260, 0, 0, 0};

struct __align__(16) AngRec {
    float Ax, Bx, Ay, By;       // x0p = sx*Ax+Bx ; y0p = sx*Ay+By (post-swap)
    float dxp, dyp, idx_, idy_; // step deltas + reciprocals (post-swap)
    int   kn, base, pad0, pad1; // shear, table element base
};
__device__ AngRec g_ang[N_ANG];

__device__ __forceinline__ unsigned h2_bits(__half2 h)
{
    return *reinterpret_cast<unsigned*>(&h);
}
__device__ __forceinline__ __half2 bits_h2(unsigned u)
{
    return *reinterpret_cast<__half2*>(&u);
}

// ---------------- per-angle precompute ----------------
__global__ __launch_bounds__(256) void build_angles()
{
    const int a = blockIdx.x * 256 + threadIdx.x;
    if (a >= N_ANG) return;

    const float ang = fmaf((float)a, (float)(M_PI / 511.0), (float)(M_PI / 2.0));
    const float sa = sinf(ang);
    const float ca = cosf(ang);
    const float SQRT2 = 1.41421356237309515f;

    float Ax = 255.5f * ca;
    float Bx = fmaf(SQRT2 * sa, 255.5f, 255.5f + (float)PAD);
    float Ay = 255.5f * sa;
    float By = fmaf(-SQRT2 * ca, 255.5f, 255.5f + (float)PAD);
    float dxp = -2.0f * SQRT2 * sa * (255.5f / 256.0f);
    float dyp =  2.0f * SQRT2 * ca * (255.5f / 256.0f);

    const int orient = (fabsf(sa) > fabsf(ca)) ? 1 : 0;
    float cxp = ca, cyp = sa;
    if (orient) {
        float t;
        t = Ax; Ax = Ay; Ay = t;
        t = Bx; Bx = By; By = t;
        t = dxp; dxp = dyp; dyp = t;
        cxp = sa; cyp = ca;
    }

    int kn = __float2int_rn(-2.0f * cyp / cxp);
    kn = max(-2, min(2, kn));

    AngRec r;
    r.Ax = Ax; r.Bx = Bx; r.Ay = Ay; r.By = By;
    r.dxp = dxp; r.dyp = dyp;
    r.idx_ = (dxp != 0.0f) ? (1.0f / dxp) : 1.0e30f;
    r.idy_ = (dyp != 0.0f) ? (1.0f / dyp) : 1.0e30f;
    r.kn = kn;
    r.base = (c_rowstart[orient * 5 + (kn + 2)] + c_off[kn + 2]) * TW;
    r.pad0 = 0; r.pad1 = 0;
    g_ang[a] = r;
}

// ---------------- fused table build ----------------
__global__ __launch_bounds__(256) void build_tables(const float* __restrict__ img)
{
    __shared__ float sm[34 * 35];

    const int tx = threadIdx.x;              // 0..31
    const int ty = threadIdx.y;              // 0..7
    const int tid = ty * 32 + tx;
    const int base_r = blockIdx.y * 32 - PAD;
    const int base_c = blockIdx.x * 32 - PAD;

    for (int idx = tid; idx < 34 * 34; idx += 256) {
        const int li = idx / 34, lj = idx % 34;
        const int r = base_r + li, c = base_c + lj;
        const bool v = ((unsigned)r < (unsigned)IMG_N) && ((unsigned)c < (unsigned)IMG_N);
        sm[li * 35 + lj] = v ? img[r * IMG_N + c] : 0.0f;
    }
    __syncthreads();

    #pragma unroll
    for (int k = 0; k < 4; ++k) {
        const int i = ty + 8 * k;            // local row 0..31

        // ---- orient 0: table tile (row=by, col=bx) ----
        const int py = blockIdx.y * 32 + i;
        const int px = blockIdx.x * 32 + tx;
        if (py < TW && px < TW) {
            uint2 q;
            q.x = h2_bits(__floats2half2_rn(sm[i * 35 + tx],       sm[i * 35 + tx + 1]));
            q.y = h2_bits(__floats2half2_rn(sm[(i + 1) * 35 + tx], sm[(i + 1) * 35 + tx + 1]));
            #pragma unroll
            for (int kn = -2; kn <= 2; ++kn) {
                const int row = c_rowstart[kn + 2] + c_off[kn + 2]
                              + py + ((kn * px) >> 1);
                g_tabs[row * TW + px] = q;
            }
        }

        // ---- orient 1 (transposed img): table tile (row=bx, col=by) ----
        const int py2 = blockIdx.x * 32 + i;
        const int px2 = blockIdx.y * 32 + tx;
        if (py2 < TW && px2 < TW) {
            uint2 q;                         // zT(r,c)=z(c,r): transposed smem read
            q.x = h2_bits(__floats2half2_rn(sm[tx * 35 + i],     sm[(tx + 1) * 35 + i]));
            q.y = h2_bits(__floats2half2_rn(sm[tx * 35 + i + 1], sm[(tx + 1) * 35 + i + 1]));
            #pragma unroll
            for (int kn = -2; kn <= 2; ++kn) {
                const int row = c_rowstart[5 + kn + 2] + c_off[kn + 2]
                              + py2 + ((kn * px2) >> 1);
                g_tabs[row * TW + px2] = q;
            }
        }
    }
}

// ---------------- radon ----------------
// one bilinear sample at (x, y); packed half2 y-blend, fp32 x-blend
template<bool ODD>
__device__ __forceinline__ void sample_one(
    const uint2* __restrict__ tp, float x, float y, int M, int kn, float& sum)
{
    const float xf = floorf(x);
    const float yf = floorf(y);
    const float fx = x - xf;
    const float fy = y - yf;
    const int ix = (int)xf;
    const int iy = (int)yf;

    int idx;
    if (ODD) idx = (iy + ((kn * ix) >> 1)) * TW + ix;
    else     idx = iy * TW + ix * M;

    const uint2 qh = __ldg(tp + idx);
    const __half2 t = bits_h2(qh.x);            // (q00, q01)
    const __half2 b = bits_h2(qh.y);            // (q10, q11)
    const __half2 fy2 = __float2half2_rn(fy);
    const __half2 m = __hfma2(fy2, __hsub2(b, t), t);   // (left, right) y-blend
    const float2 mf = __half22float2(m);

    sum += fmaf(fx, mf.y - mf.x, mf.x);
}

template<bool ODD>
__device__ __forceinline__ float integrate(
    const uint2* __restrict__ tp,
    float x0p, float y0p, float dxp, float dyp,
    int s0, int s1, int M, int kn)
{
    float sum = 0.0f;
    const int n = s1 - s0 + 1;
    float sbf = (float)s0;                    // exact
    int i = 0;

    for (; i + 8 <= n; i += 8) {
        const float xb = fmaf(sbf, dxp, x0p); // exact integer base -> no drift
        const float yb = fmaf(sbf, dyp, y0p);
        sbf += 8.0f;
        #pragma unroll
        for (int j = 0; j < 8; ++j) {
            const float x = fmaf((float)j, dxp, xb);   // FFMA-imm
            const float y = fmaf((float)j, dyp, yb);
            sample_one<ODD>(tp, x, y, M, kn, sum);
        }
    }
    if (i < n) {
        const float xb = fmaf(sbf, dxp, x0p);
        const float yb = fmaf(sbf, dyp, y0p);
        for (int j = 0; i + j < n; ++j) {
            const float x = fmaf((float)j, dxp, xb);
            const float y = fmaf((float)j, dyp, yb);
            sample_one<ODD>(tp, x, y, M, kn, sum);
        }
    }
    return sum;
}

__global__ __launch_bounds__(256, 7) void radon_fwd_kernel(float* __restrict__ out)
{
    const int widx = threadIdx.x >> 5;
    const int lane = threadIdx.x & 31;
    const int wg   = blockIdx.x * 8 + widx;   // 0..16383

    const int h   = wg & 1;                   // s-half
    const int rid = wg >> 1;                  // 0..8191

    const int a     = (rid * 341) & 511;      // angle permutation (balance)
    const int chunk = rid >> 9;               // 0..15
    const int d     = chunk * 32 + lane;      // detector

    const AngRec r = g_ang[a];                // warp-uniform load

    const float sx  = fmaf((float)d, 2.0f / 511.0f, -1.0f);
    const float x0p = fmaf(sx, r.Ax, r.Bx);
    const float y0p = fmaf(sx, r.Ay, r.By);

    // clip sample range to table interior [1, 517] via reciprocal multiplies
    const float L = 1.0f, H = (float)(TW - 3);
    float lo = 0.0f, hi = (float)(N_SAMP - 1);
    {
        const float t0 = (L - x0p) * r.idx_;
        const float t1 = (H - x0p) * r.idx_;
        lo = fmaxf(lo, fminf(t0, t1));
        hi = fminf(hi, fmaxf(t0, t1));
        const float u0 = (L - y0p) * r.idy_;
        const float u1 = (H - y0p) * r.idy_;
        lo = fmaxf(lo, fminf(u0, u1));
        hi = fminf(hi, fmaxf(u0, u1));
    }
    int s0 = (lo > 0.0f) ? (int)ceilf(lo) : 0;
    int s1 = (hi < (float)(N_SAMP - 1)) ? (int)floorf(hi) : (N_SAMP - 1);

    const int hs0 = h * (N_SAMP / 2);
    const int hs1 = hs0 + (N_SAMP / 2) - 1;
    s0 = max(s0, hs0);
    s1 = min(s1, hs1);
    if (s0 > s1) return;

    const uint2* tp = g_tabs + r.base;
    const int kn    = r.kn;
    const int M     = 1 + (kn >> 1) * TW;     // even-kn column multiplier

    float sum;
    if (kn & 1) sum = integrate<true >(tp, x0p, y0p, r.dxp, r.dyp, s0, s1, M, kn);
    else        sum = integrate<false>(tp, x0p, y0p, r.dxp, r.dyp, s0, s1, M, kn);

    const int o = (N_ANG - 1 - a) * N_DET + (N_DET - 1 - d);
    atomicAdd(out + o, sum * (1.0f / (float)N_SAMP));
}

extern "C" void kernel_launch(void* const* d_in, const int* in_sizes, int n_in,
                              void* d_out, int out_size)
{
    const float* img = (const float*)d_in[0];
    float* out = (float*)d_out;

    cudaMemsetAsync(out, 0, N_ANG * N_DET * sizeof(float));

    build_angles<<<2, 256>>>();

    dim3 bt(32, 8);
    dim3 bg((TW + 31) / 32, (TW + 31) / 32);   // 17 x 17 tiles
    build_tables<<<bg, bt>>>(img);

    // 512 angles * 16 det-warps * 2 s-halves = 16384 warps = 2048 blocks of 256
    radon_fwd_kernel<<<2048, 256>>>(out);
}

// round 14
// speedup vs baseline: 1.0276x; 1.0276x over previous
#include <cuda_runtime.h>
#include <cuda_fp16.h>
#include <math.h>

// Radon forward projection, 512x512 img -> [512,512] sinogram (both axes flipped).
// R13: fuse per-angle precompute into build_tables (kills the 4.8us extra
//      launch), cap regs at 32 via launch_bounds(256,8) for occupancy.
//      Memory layout unchanged: fp16x2 quad tables, 5 shears x 2 orients
//      (35 MB, L2-resident), one LDG.64 per bilinear sample, HFMA2 y-blend.

#define IMG_N   512
#define N_ANG   512
#define N_DET   512
#define N_SAMP  256

#define PAD     3
#define TW      (IMG_N + 2*PAD + 2)     // 520

#define TOT_ROWS 8320                   // 2 orients x (1040+780+520+780+1040)

// entry: .x = half2(q00,q01) (top row), .y = half2(q10,q11) (bottom row)
__device__ uint2 g_tabs[TOT_ROWS * TW];     // 34.6 MB

// row starts for (orient, kn): orient*5 + (kn+2)
__device__ __constant__ int c_rowstart[10] =
    {0, 1040, 1820, 2340, 3120,  4160, 5200, 5980, 6500, 7280};
__device__ __constant__ int c_off[5] = {519, 260, 0, 0, 0};

struct __align__(16) AngRec {
    float Ax, Bx, Ay, By;       // x0p = sx*Ax+Bx ; y0p = sx*Ay+By (post-swap)
    float dxp, dyp, idx_, idy_; // step deltas + reciprocals (post-swap)
    int   kn, base, pad0, pad1; // shear, table element base
};
__device__ AngRec g_ang[N_ANG];

__device__ __forceinline__ unsigned h2_bits(__half2 h)
{
    return *reinterpret_cast<unsigned*>(&h);
}
__device__ __forceinline__ __half2 bits_h2(unsigned u)
{
    return *reinterpret_cast<__half2*>(&u);
}

__device__ __forceinline__ void make_angrec(int a)
{
    const float ang = fmaf((float)a, (float)(M_PI / 511.0), (float)(M_PI / 2.0));
    const float sa = sinf(ang);
    const float ca = cosf(ang);
    const float SQRT2 = 1.41421356237309515f;

    float Ax = 255.5f * ca;
    float Bx = fmaf(SQRT2 * sa, 255.5f, 255.5f + (float)PAD);
    float Ay = 255.5f * sa;
    float By = fmaf(-SQRT2 * ca, 255.5f, 255.5f + (float)PAD);
    float dxp = -2.0f * SQRT2 * sa * (255.5f / 256.0f);
    float dyp =  2.0f * SQRT2 * ca * (255.5f / 256.0f);

    const int orient = (fabsf(sa) > fabsf(ca)) ? 1 : 0;
    float cxp = ca, cyp = sa;
    if (orient) {
        float t;
        t = Ax; Ax = Ay; Ay = t;
        t = Bx; Bx = By; By = t;
        t = dxp; dxp = dyp; dyp = t;
        cxp = sa; cyp = ca;
    }

    int kn = __float2int_rn(-2.0f * cyp / cxp);
    kn = max(-2, min(2, kn));

    AngRec r;
    r.Ax = Ax; r.Bx = Bx; r.Ay = Ay; r.By = By;
    r.dxp = dxp; r.dyp = dyp;
    r.idx_ = (dxp != 0.0f) ? (1.0f / dxp) : 1.0e30f;
    r.idy_ = (dyp != 0.0f) ? (1.0f / dyp) : 1.0e30f;
    r.kn = kn;
    r.base = (c_rowstart[orient * 5 + (kn + 2)] + c_off[kn + 2]) * TW;
    r.pad0 = 0; r.pad1 = 0;
    g_ang[a] = r;
}

// ---------------- fused table + angle build ----------------
__global__ __launch_bounds__(256) void build_tables(const float* __restrict__ img)
{
    __shared__ float sm[34 * 35];

    const int tx = threadIdx.x;              // 0..31
    const int ty = threadIdx.y;              // 0..7
    const int tid = ty * 32 + tx;

    // block (0,0) also fills the per-angle table (2 angles per thread)
    if (blockIdx.x == 0 && blockIdx.y == 0) {
        make_angrec(tid);
        make_angrec(tid + 256);
    }

    const int base_r = blockIdx.y * 32 - PAD;
    const int base_c = blockIdx.x * 32 - PAD;

    for (int idx = tid; idx < 34 * 34; idx += 256) {
        const int li = idx / 34, lj = idx % 34;
        const int r = base_r + li, c = base_c + lj;
        const bool v = ((unsigned)r < (unsigned)IMG_N) && ((unsigned)c < (unsigned)IMG_N);
        sm[li * 35 + lj] = v ? img[r * IMG_N + c] : 0.0f;
    }
    __syncthreads();

    #pragma unroll
    for (int k = 0; k < 4; ++k) {
        const int i = ty + 8 * k;            // local row 0..31

        // ---- orient 0: table tile (row=by, col=bx) ----
        const int py = blockIdx.y * 32 + i;
        const int px = blockIdx.x * 32 + tx;
        if (py < TW && px < TW) {
            uint2 q;
            q.x = h2_bits(__floats2half2_rn(sm[i * 35 + tx],       sm[i * 35 + tx + 1]));
            q.y = h2_bits(__floats2half2_rn(sm[(i + 1) * 35 + tx], sm[(i + 1) * 35 + tx + 1]));
            #pragma unroll
            for (int kn = -2; kn <= 2; ++kn) {
                const int row = c_rowstart[kn + 2] + c_off[kn + 2]
                              + py + ((kn * px) >> 1);
                g_tabs[row * TW + px] = q;
            }
        }

        // ---- orient 1 (transposed img): table tile (row=bx, col=by) ----
        const int py2 = blockIdx.x * 32 + i;
        const int px2 = blockIdx.y * 32 + tx;
        if (py2 < TW && px2 < TW) {
            uint2 q;                         // zT(r,c)=z(c,r): transposed smem read
            q.x = h2_bits(__floats2half2_rn(sm[tx * 35 + i],     sm[(tx + 1) * 35 + i]));
            q.y = h2_bits(__floats2half2_rn(sm[tx * 35 + i + 1], sm[(tx + 1) * 35 + i + 1]));
            #pragma unroll
            for (int kn = -2; kn <= 2; ++kn) {
                const int row = c_rowstart[5 + kn + 2] + c_off[kn + 2]
                              + py2 + ((kn * px2) >> 1);
                g_tabs[row * TW + px2] = q;
            }
        }
    }
}

// ---------------- radon ----------------
// one bilinear sample at (x, y); packed half2 y-blend, fp32 x-blend
template<bool ODD>
__device__ __forceinline__ void sample_one(
    const uint2* __restrict__ tp, float x, float y, int M, int kn, float& sum)
{
    const float xf = floorf(x);
    const float yf = floorf(y);
    const float fx = x - xf;
    const float fy = y - yf;
    const int ix = (int)xf;
    const int iy = (int)yf;

    int idx;
    if (ODD) idx = (iy + ((kn * ix) >> 1)) * TW + ix;
    else     idx = iy * TW + ix * M;

    const uint2 qh = __ldg(tp + idx);
    const __half2 t = bits_h2(qh.x);            // (q00, q01)
    const __half2 b = bits_h2(qh.y);            // (q10, q11)
    const __half2 fy2 = __float2half2_rn(fy);
    const __half2 m = __hfma2(fy2, __hsub2(b, t), t);   // (left, right) y-blend
    const float2 mf = __half22float2(m);

    sum += fmaf(fx, mf.y - mf.x, mf.x);
}

template<bool ODD>
__device__ __forceinline__ float integrate(
    const uint2* __restrict__ tp,
    float x0p, float y0p, float dxp, float dyp,
    int s0, int s1, int M, int kn)
{
    float sum = 0.0f;
    const int n = s1 - s0 + 1;
    float sbf = (float)s0;                    // exact
    int i = 0;

    for (; i + 8 <= n; i += 8) {
        const float xb = fmaf(sbf, dxp, x0p); // exact integer base -> no drift
        const float yb = fmaf(sbf, dyp, y0p);
        sbf += 8.0f;
        #pragma unroll
        for (int j = 0; j < 8; ++j) {
            const float x = fmaf((float)j, dxp, xb);   // FFMA-imm
            const float y = fmaf((float)j, dyp, yb);
            sample_one<ODD>(tp, x, y, M, kn, sum);
        }
    }
    if (i < n) {
        const float xb = fmaf(sbf, dxp, x0p);
        const float yb = fmaf(sbf, dyp, y0p);
        for (int j = 0; i + j < n; ++j) {
            const float x = fmaf((float)j, dxp, xb);
            const float y = fmaf((float)j, dyp, yb);
            sample_one<ODD>(tp, x, y, M, kn, sum);
        }
    }
    return sum;
}

__global__ __launch_bounds__(256, 8) void radon_fwd_kernel(float* __restrict__ out)
{
    const int widx = threadIdx.x >> 5;
    const int lane = threadIdx.x & 31;
    const int wg   = blockIdx.x * 8 + widx;   // 0..16383

    const int h   = wg & 1;                   // s-half
    const int rid = wg >> 1;                  // 0..8191

    const int a     = (rid * 341) & 511;      // angle permutation (balance)
    const int chunk = rid >> 9;               // 0..15
    const int d     = chunk * 32 + lane;      // detector

    const AngRec r = g_ang[a];                // warp-uniform load

    const float sx  = fmaf((float)d, 2.0f / 511.0f, -1.0f);
    const float x0p = fmaf(sx, r.Ax, r.Bx);
    const float y0p = fmaf(sx, r.Ay, r.By);

    // clip sample range to table interior [1, 517] via reciprocal multiplies
    const float L = 1.0f, H = (float)(TW - 3);
    float lo = 0.0f, hi = (float)(N_SAMP - 1);
    {
        const float t0 = (L - x0p) * r.idx_;
        const float t1 = (H - x0p) * r.idx_;
        lo = fmaxf(lo, fminf(t0, t1));
        hi = fminf(hi, fmaxf(t0, t1));
        const float u0 = (L - y0p) * r.idy_;
        const float u1 = (H - y0p) * r.idy_;
        lo = fmaxf(lo, fminf(u0, u1));
        hi = fminf(hi, fmaxf(u0, u1));
    }
    int s0 = (lo > 0.0f) ? (int)ceilf(lo) : 0;
    int s1 = (hi < (float)(N_SAMP - 1)) ? (int)floorf(hi) : (N_SAMP - 1);

    const int hs0 = h * (N_SAMP / 2);
    const int hs1 = hs0 + (N_SAMP / 2) - 1;
    s0 = max(s0, hs0);
    s1 = min(s1, hs1);
    if (s0 > s1) return;

    const uint2* tp = g_tabs + r.base;
    const int kn    = r.kn;
    const int M     = 1 + (kn >> 1) * TW;     // even-kn column multiplier

    float sum;
    if (kn & 1) sum = integrate<true >(tp, x0p, y0p, r.dxp, r.dyp, s0, s1, M, kn);
    else        sum = integrate<false>(tp, x0p, y0p, r.dxp, r.dyp, s0, s1, M, kn);

    const int o = (N_ANG - 1 - a) * N_DET + (N_DET - 1 - d);
    atomicAdd(out + o, sum * (1.0f / (float)N_SAMP));
}

extern "C" void kernel_launch(void* const* d_in, const int* in_sizes, int n_in,
                              void* d_out, int out_size)
{
    const float* img = (const float*)d_in[0];
    float* out = (float*)d_out;

    cudaMemsetAsync(out, 0, N_ANG * N_DET * sizeof(float));

    dim3 bt(32, 8);
    dim3 bg((TW + 31) / 32, (TW + 31) / 32);   // 17 x 17 tiles
    build_tables<<<bg, bt>>>(img);

    // 512 angles * 16 det-warps * 2 s-halves = 16384 warps = 2048 blocks of 256
    radon_fwd_kernel<<<2048, 256>>>(out);
}